// round 2
// baseline (speedup 1.0000x reference)
#include <cuda_runtime.h>
#include <math.h>

#define Bv 8
#define Tv 4096
#define Dv 1024
#define EPS 0.01
#define TT 64                  // timesteps per block in main pass
#define TILES (Tv / TT)        // 64

// Device scratch (no allocations allowed in kernel_launch)
__device__ float d_coef[Bv * Tv];                   // eps*g_t * suffix-product of c_r (r>t)
__device__ float d_y[Bv * Tv];                      // x_t . w
__device__ float d_mempart[(size_t)Bv * TILES * Dv]; // per-tile memory partials

// ---------------------------------------------------------------------------
// Kernel A: per-batch suffix products of c_t = 1 - eps*g_t  ->  coef[b,t]
// 8 blocks x 128 threads, 32 timesteps per thread, double precision.
// ---------------------------------------------------------------------------
__global__ void coef_kernel(const int* __restrict__ pad,
                            const int* __restrict__ upd) {
    const int b = blockIdx.x;
    const int i = threadIdx.x;           // 0..127
    const int CH = 32;
    __shared__ double sP[128];

    // chunk product
    double P = 1.0;
#pragma unroll
    for (int k = 0; k < CH; k++) {
        int t = i * CH + k;
        bool g = (pad[b * Tv + t] == 0) && (upd[b * Tv + t] != 0);
        if (g) P *= (1.0 - EPS);
    }
    sP[i] = P;
    __syncthreads();

    // inclusive suffix scan (product) across 128 chunks
    for (int off = 1; off < 128; off <<= 1) {
        double pr = (i + off < 128) ? sP[i + off] : 1.0;
        double cur = sP[i];
        __syncthreads();
        sP[i] = cur * pr;
        __syncthreads();
    }
    double running = (i == 127) ? 1.0 : sP[i + 1];  // product of all chunks after mine

    // replay chunk backwards: coef[t] = eps*g_t * prod_{r>t} c_r
    for (int k = CH - 1; k >= 0; k--) {
        int t = i * CH + k;
        bool g = (pad[b * Tv + t] == 0) && (upd[b * Tv + t] != 0);
        d_coef[b * Tv + t] = g ? (float)(EPS * running) : 0.0f;
        if (g) running *= (1.0 - EPS);
    }
}

// ---------------------------------------------------------------------------
// Kernel B: single streaming pass over write_signal (128 MB).
// Produces: y[b,t] = x_t . w   (row-per-warp GEMV, warp shuffle reduce)
//           mempart[b,tile,d] = sum_{t in tile} coef[b,t]*x_t[d] (registers)
// grid = (TILES, Bv), 256 threads (8 warps). Warp handles rows t0+warp, +8,...
// Lane owns d = j*128 + lane*4 for j=0..7 (float4). Deterministic, no atomics.
// ---------------------------------------------------------------------------
__global__ void __launch_bounds__(256) main_kernel(const float* __restrict__ x,
                                                   const float* __restrict__ w) {
    const int b = blockIdx.y;
    const int t0 = blockIdx.x * TT;
    const int warp = threadIdx.x >> 5;
    const int lane = threadIdx.x & 31;

    float4 wv[8];
#pragma unroll
    for (int j = 0; j < 8; j++) wv[j] = __ldg(&((const float4*)w)[j * 32 + lane]);

    float4 macc[8];
#pragma unroll
    for (int j = 0; j < 8; j++) macc[j] = make_float4(0.f, 0.f, 0.f, 0.f);

    for (int r = warp; r < TT; r += 8) {
        const int t = t0 + r;
        const float4* row = (const float4*)(x + ((size_t)(b * Tv + t)) * Dv);
        const float c = d_coef[b * Tv + t];
        float dot = 0.f;
#pragma unroll
        for (int j = 0; j < 8; j++) {
            float4 v = __ldg(&row[j * 32 + lane]);
            dot += v.x * wv[j].x + v.y * wv[j].y + v.z * wv[j].z + v.w * wv[j].w;
            macc[j].x += c * v.x;
            macc[j].y += c * v.y;
            macc[j].z += c * v.z;
            macc[j].w += c * v.w;
        }
#pragma unroll
        for (int off = 16; off; off >>= 1)
            dot += __shfl_down_sync(0xffffffffu, dot, off);
        if (lane == 0) d_y[b * Tv + t] = dot;
    }

    // combine 8 warps' memory partials deterministically via shared memory
    __shared__ float smem[Dv];
    for (int wsel = 0; wsel < 8; wsel++) {
        if (warp == wsel) {
#pragma unroll
            for (int j = 0; j < 8; j++) {
                int d = j * 128 + lane * 4;
                if (wsel == 0) {
                    smem[d + 0] = macc[j].x; smem[d + 1] = macc[j].y;
                    smem[d + 2] = macc[j].z; smem[d + 3] = macc[j].w;
                } else {
                    smem[d + 0] += macc[j].x; smem[d + 1] += macc[j].y;
                    smem[d + 2] += macc[j].z; smem[d + 3] += macc[j].w;
                }
            }
        }
        __syncthreads();
    }
    float4* dst = (float4*)&d_mempart[((size_t)b * TILES + blockIdx.x) * Dv];
    const float4* s4 = (const float4*)smem;
    dst[threadIdx.x] = s4[threadIdx.x];  // 256 threads x float4 = 1024 floats
}

// ---------------------------------------------------------------------------
// Kernel C: per-batch parallel affine scan u_t = c_t*u_{t-1} + eps*g_t*y_t,
// then bias = pad ? 1 : clip(1 + tanh(u), 0.8, 1.2). 8 blocks x 128 threads.
// ---------------------------------------------------------------------------
__global__ void scan_kernel(const int* __restrict__ pad,
                            const int* __restrict__ upd,
                            float* __restrict__ out) {
    const int b = blockIdx.x;
    const int i = threadIdx.x;
    const int CH = 32;
    __shared__ double sC[128], sA[128];

    // compose affine transforms over my chunk (in order)
    double C = 1.0, A = 0.0;
#pragma unroll
    for (int k = 0; k < CH; k++) {
        int t = i * CH + k;
        bool g = (pad[b * Tv + t] == 0) && (upd[b * Tv + t] != 0);
        if (g) {
            A = (1.0 - EPS) * A + EPS * (double)d_y[b * Tv + t];
            C *= (1.0 - EPS);
        }
    }
    sC[i] = C; sA[i] = A;
    __syncthreads();

    // inclusive prefix scan of affine composition across chunks
    for (int off = 1; off < 128; off <<= 1) {
        double pC = 1.0, pA = 0.0;
        if (i >= off) { pC = sC[i - off]; pA = sA[i - off]; }
        double cS = sC[i], aS = sA[i];
        __syncthreads();
        sC[i] = cS * pC;
        sA[i] = cS * pA + aS;
        __syncthreads();
    }

    // u at the start of my chunk (u0 = 0 -> exclusive prefix is just A)
    double u = (i == 0) ? 0.0 : sA[i - 1];

    for (int k = 0; k < CH; k++) {
        int t = i * CH + k;
        bool p = (pad[b * Tv + t] != 0);
        bool g = (!p) && (upd[b * Tv + t] != 0);
        if (g) u = (1.0 - EPS) * u + EPS * (double)d_y[b * Tv + t];
        float bias;
        if (p) {
            bias = 1.0f;
        } else {
            bias = 1.0f + tanhf((float)u);
            bias = fminf(fmaxf(bias, 0.8f), 1.2f);
        }
        out[b * Tv + t] = bias;
    }
}

// ---------------------------------------------------------------------------
// Kernel D: memory[b,d] = sum over TILES partials (deterministic fixed order)
// ---------------------------------------------------------------------------
__global__ void memred_kernel(float* __restrict__ out) {
    int idx = blockIdx.x * blockDim.x + threadIdx.x;  // over Bv*Dv = 8192
    if (idx >= Bv * Dv) return;
    int b = idx / Dv, d = idx - b * Dv;
    float s = 0.f;
#pragma unroll 8
    for (int tile = 0; tile < TILES; tile++)
        s += d_mempart[((size_t)b * TILES + tile) * Dv + d];
    out[Bv * Tv + idx] = s;
}

// ---------------------------------------------------------------------------
extern "C" void kernel_launch(void* const* d_in, const int* in_sizes, int n_in,
                              void* d_out, int out_size) {
    const float* x = (const float*)d_in[0];            // write_signal (8,4096,1024)
    const int* pad = (const int*)d_in[1];              // pad_mask bool -> int32 (8,4096)
    const int* upd = (const int*)d_in[2];              // update_mask bool -> int32 (8,4096)
    const float* w = (const float*)d_in[3];            // w (1024,)
    float* out = (float*)d_out;                        // [bias (8*4096) | memory (8*1024)]

    coef_kernel<<<Bv, 128>>>(pad, upd);
    dim3 grid(TILES, Bv);
    main_kernel<<<grid, 256>>>(x, w);
    scan_kernel<<<Bv, 128>>>(pad, upd, out);
    memred_kernel<<<(Bv * Dv + 255) / 256, 256>>>(out);
}

// round 3
// speedup vs baseline: 1.5068x; 1.5068x over previous
#include <cuda_runtime.h>
#include <math.h>

#define Bv 8
#define Tv 4096
#define Dv 1024
#define EPS 0.01
#define TT 64                  // timesteps per block in main pass
#define TILES (Tv / TT)        // 64

// Device scratch (no allocations allowed in kernel_launch)
__device__ float d_coef[Bv * Tv];                    // eps*g_t * suffix-product of c_r (r>t)
__device__ float d_y[Bv * Tv];                       // x_t . w
__device__ float d_mempart[(size_t)Bv * TILES * Dv]; // per-tile memory partials

// ---------------------------------------------------------------------------
// Kernel A: per-batch suffix products of c_t = 1 - eps*g_t  ->  coef[b,t]
// 8 blocks x 256 threads, 16 timesteps per thread, double precision scan.
// ---------------------------------------------------------------------------
__global__ void __launch_bounds__(256) coef_kernel(const int* __restrict__ pad,
                                                   const int* __restrict__ upd) {
    const int b = blockIdx.x;
    const int i = threadIdx.x;           // 0..255
    __shared__ double sP[256];

    // vectorized mask loads: 16 timesteps = 4 int4 each
    const int4* p4 = (const int4*)(pad + b * Tv);
    const int4* u4 = (const int4*)(upd + b * Tv);
    int pv[16], uv[16];
#pragma unroll
    for (int q = 0; q < 4; q++) {
        int4 a = __ldg(&p4[i * 4 + q]);
        int4 c = __ldg(&u4[i * 4 + q]);
        pv[q * 4 + 0] = a.x; pv[q * 4 + 1] = a.y; pv[q * 4 + 2] = a.z; pv[q * 4 + 3] = a.w;
        uv[q * 4 + 0] = c.x; uv[q * 4 + 1] = c.y; uv[q * 4 + 2] = c.z; uv[q * 4 + 3] = c.w;
    }

    bool g[16];
    double P = 1.0;
#pragma unroll
    for (int k = 0; k < 16; k++) {
        g[k] = (pv[k] == 0) && (uv[k] != 0);
        if (g[k]) P *= (1.0 - EPS);
    }
    sP[i] = P;
    __syncthreads();

    // inclusive suffix scan (product) across 256 chunks
    for (int off = 1; off < 256; off <<= 1) {
        double pr = (i + off < 256) ? sP[i + off] : 1.0;
        double cur = sP[i];
        __syncthreads();
        sP[i] = cur * pr;
        __syncthreads();
    }
    double running = (i == 255) ? 1.0 : sP[i + 1];  // product of all chunks after mine

    // replay chunk backwards: coef[t] = eps*g_t * prod_{r>t} c_r
#pragma unroll
    for (int k = 15; k >= 0; k--) {
        int t = i * 16 + k;
        d_coef[b * Tv + t] = g[k] ? (float)(EPS * running) : 0.0f;
        if (g[k]) running *= (1.0 - EPS);
    }
}

// ---------------------------------------------------------------------------
// Kernel B: single streaming pass over write_signal (128 MB).
// Produces: y[b,t] = x_t . w   (row-per-warp GEMV, warp shuffle reduce)
//           mempart[b,tile,d] = sum_{t in tile} coef[b,t]*x_t[d] (registers)
// grid = (TILES, Bv), 256 threads (8 warps). Streaming (__ldcs) loads.
// ---------------------------------------------------------------------------
__global__ void __launch_bounds__(256) main_kernel(const float* __restrict__ x,
                                                   const float* __restrict__ w) {
    const int b = blockIdx.y;
    const int t0 = blockIdx.x * TT;
    const int warp = threadIdx.x >> 5;
    const int lane = threadIdx.x & 31;

    float4 wv[8];
#pragma unroll
    for (int j = 0; j < 8; j++) wv[j] = __ldg(&((const float4*)w)[j * 32 + lane]);

    float4 macc[8];
#pragma unroll
    for (int j = 0; j < 8; j++) macc[j] = make_float4(0.f, 0.f, 0.f, 0.f);

    for (int r = warp; r < TT; r += 8) {
        const int t = t0 + r;
        const float4* row = (const float4*)(x + ((size_t)(b * Tv + t)) * Dv);
        const float c = d_coef[b * Tv + t];
        float dot = 0.f;
#pragma unroll
        for (int j = 0; j < 8; j++) {
            float4 v = __ldcs(&row[j * 32 + lane]);   // read-once: stream past L2
            dot += v.x * wv[j].x + v.y * wv[j].y + v.z * wv[j].z + v.w * wv[j].w;
            macc[j].x += c * v.x;
            macc[j].y += c * v.y;
            macc[j].z += c * v.z;
            macc[j].w += c * v.w;
        }
#pragma unroll
        for (int off = 16; off; off >>= 1)
            dot += __shfl_down_sync(0xffffffffu, dot, off);
        if (lane == 0) d_y[b * Tv + t] = dot;
    }

    // combine 8 warps' memory partials deterministically via shared memory
    __shared__ float smem[Dv];
    for (int wsel = 0; wsel < 8; wsel++) {
        if (warp == wsel) {
#pragma unroll
            for (int j = 0; j < 8; j++) {
                int d = j * 128 + lane * 4;
                if (wsel == 0) {
                    smem[d + 0] = macc[j].x; smem[d + 1] = macc[j].y;
                    smem[d + 2] = macc[j].z; smem[d + 3] = macc[j].w;
                } else {
                    smem[d + 0] += macc[j].x; smem[d + 1] += macc[j].y;
                    smem[d + 2] += macc[j].z; smem[d + 3] += macc[j].w;
                }
            }
        }
        __syncthreads();
    }
    float4* dst = (float4*)&d_mempart[((size_t)b * TILES + blockIdx.x) * Dv];
    const float4* s4 = (const float4*)smem;
    dst[threadIdx.x] = s4[threadIdx.x];  // 256 threads x float4 = 1024 floats
}

// ---------------------------------------------------------------------------
// Kernel C (fused): blocks 0..7  -> per-batch affine scan + bias output
//                   blocks 8..71 -> memory reduction over TILES partials
// Both depend only on main_kernel outputs, so they run concurrently.
// ---------------------------------------------------------------------------
__global__ void __launch_bounds__(256) epilogue_kernel(const int* __restrict__ pad,
                                                       float* __restrict__ out) {
    if (blockIdx.x < Bv) {
        // ---------------- scan part: u_t = c_t*u_{t-1} + eps*g_t*y_t ----------
        const int b = blockIdx.x;
        const int i = threadIdx.x;      // 0..255, 16 timesteps each
        __shared__ double sC[256], sA[256];

        float cf[16], yv[16];
        int pv[16];
        const int4* p4 = (const int4*)(pad + b * Tv);
#pragma unroll
        for (int q = 0; q < 4; q++) {
            int4 a = __ldg(&p4[i * 4 + q]);
            pv[q * 4 + 0] = a.x; pv[q * 4 + 1] = a.y; pv[q * 4 + 2] = a.z; pv[q * 4 + 3] = a.w;
            float4 cfv = *((const float4*)&d_coef[b * Tv + i * 16 + q * 4]);
            cf[q * 4 + 0] = cfv.x; cf[q * 4 + 1] = cfv.y; cf[q * 4 + 2] = cfv.z; cf[q * 4 + 3] = cfv.w;
            float4 yvv = *((const float4*)&d_y[b * Tv + i * 16 + q * 4]);
            yv[q * 4 + 0] = yvv.x; yv[q * 4 + 1] = yvv.y; yv[q * 4 + 2] = yvv.z; yv[q * 4 + 3] = yvv.w;
        }

        // compose affine transforms over my chunk (in order); gate = coef>0
        double C = 1.0, A = 0.0;
#pragma unroll
        for (int k = 0; k < 16; k++) {
            if (cf[k] > 0.0f) {
                A = (1.0 - EPS) * A + EPS * (double)yv[k];
                C *= (1.0 - EPS);
            }
        }
        sC[i] = C; sA[i] = A;
        __syncthreads();

        // inclusive prefix scan of affine composition across chunks
        for (int off = 1; off < 256; off <<= 1) {
            double pC = 1.0, pA = 0.0;
            if (i >= off) { pC = sC[i - off]; pA = sA[i - off]; }
            double cS = sC[i], aS = sA[i];
            __syncthreads();
            sC[i] = cS * pC;
            sA[i] = cS * pA + aS;
            __syncthreads();
        }

        // u at start of my chunk (u0 = 0 -> exclusive prefix is A of previous)
        double u = (i == 0) ? 0.0 : sA[i - 1];

        float ob[16];
#pragma unroll
        for (int k = 0; k < 16; k++) {
            bool p = (pv[k] != 0);
            if (cf[k] > 0.0f) u = (1.0 - EPS) * u + EPS * (double)yv[k];
            float bias;
            if (p) {
                bias = 1.0f;
            } else {
                bias = 1.0f + tanhf((float)u);
                bias = fminf(fmaxf(bias, 0.8f), 1.2f);
            }
            ob[k] = bias;
        }
        float4* o4 = (float4*)(out + b * Tv + i * 16);
#pragma unroll
        for (int q = 0; q < 4; q++)
            o4[q] = make_float4(ob[q * 4], ob[q * 4 + 1], ob[q * 4 + 2], ob[q * 4 + 3]);
    } else {
        // ---------------- memred part: memory[b,d] = sum_tiles partials --------
        // 64 blocks; each block covers 32 float4 outputs; tid = oi*8 + sub;
        // lane-group of 8 splits the 64 tiles (8 tiles each) -> shuffle reduce.
        const int m = blockIdx.x - Bv;          // 0..63
        const int tid = threadIdx.x;
        const int oi = tid >> 3;                // 0..31
        const int sub = tid & 7;                // 0..7
        const int o4 = m * 32 + oi;             // 0..2047 (float4 index over B*D)
        const int b = o4 >> 8;                  // Dv/4 = 256 float4 per batch
        const int d4 = o4 & 255;

        const float4* mp4 = (const float4*)d_mempart;
        float4 s = make_float4(0.f, 0.f, 0.f, 0.f);
#pragma unroll
        for (int k = 0; k < 8; k++) {
            int tile = sub * 8 + k;
            float4 v = mp4[((size_t)(b * TILES + tile)) * 256 + d4];
            s.x += v.x; s.y += v.y; s.z += v.z; s.w += v.w;
        }
        // reduce across sub (groups of 8 lanes) -- fixed tree, deterministic
#pragma unroll
        for (int off = 4; off; off >>= 1) {
            s.x += __shfl_down_sync(0xffffffffu, s.x, off);
            s.y += __shfl_down_sync(0xffffffffu, s.y, off);
            s.z += __shfl_down_sync(0xffffffffu, s.z, off);
            s.w += __shfl_down_sync(0xffffffffu, s.w, off);
        }
        if (sub == 0)
            ((float4*)(out + Bv * Tv))[o4] = s;
    }
}

// ---------------------------------------------------------------------------
extern "C" void kernel_launch(void* const* d_in, const int* in_sizes, int n_in,
                              void* d_out, int out_size) {
    const float* x = (const float*)d_in[0];            // write_signal (8,4096,1024)
    const int* pad = (const int*)d_in[1];              // pad_mask bool -> int32 (8,4096)
    const int* upd = (const int*)d_in[2];              // update_mask bool -> int32 (8,4096)
    const float* w = (const float*)d_in[3];            // w (1024,)
    float* out = (float*)d_out;                        // [bias (8*4096) | memory (8*1024)]

    coef_kernel<<<Bv, 256>>>(pad, upd);
    dim3 grid(TILES, Bv);
    main_kernel<<<grid, 256>>>(x, w);
    epilogue_kernel<<<Bv + 64, 256>>>(pad, out);
}

// round 6
// speedup vs baseline: 2.4239x; 1.6087x over previous
#include <cuda_runtime.h>
#include <math.h>

#define Bv 8
#define Tv 4096
#define Dv 1024
#define EPS 0.01f
#define TT 64                  // timesteps per block in main pass
#define TILES (Tv / TT)        // 64
#define LOG2_C (-0.014499569695115089f)   // log2(0.99)
#define LN_C   (-0.010050335853501441)    // ln(0.99), double

// Device scratch — 16B-aligned (accessed through float4 casts)
__device__ __align__(16) float d_y[Bv * Tv];                       // x_t . w
__device__ __align__(16) float d_mempart[(size_t)Bv * TILES * Dv]; // per-tile partials
__device__ __align__(16) int   d_tilecnt[Bv * TILES];              // gates per tile

// ---------------------------------------------------------------------------
// Kernel B: single streaming pass over write_signal (128 MB).
// Per block: derive tile-local coefficients from gate bits (ballot+popc+exp2f),
// then y[b,t] = x_t.w (row-per-warp GEMV) and tile-local weighted sum of x.
// grid = (TILES, Bv), 256 threads (8 warps). Deterministic, no atomics.
// ---------------------------------------------------------------------------
__global__ void __launch_bounds__(256) main_kernel(const float* __restrict__ x,
                                                   const float* __restrict__ w,
                                                   const int* __restrict__ pad,
                                                   const int* __restrict__ upd) {
    const int b = blockIdx.y;
    const int t0 = blockIdx.x * TT;
    const int tid = threadIdx.x;
    const int warp = tid >> 5;
    const int lane = tid & 31;

    // ALIGNMENT: smem is float4-cast below. Round 4/5 trap root cause: with
    // s_coef+s_mask declared first, smem landed at shared offset 264 (8 mod 16)
    // -> misaligned LDS.128. Force 16B alignment explicitly.
    __shared__ __align__(16) float smem[Dv];
    __shared__ __align__(16) float s_coef[TT];
    __shared__ unsigned s_mask[2];

    // gate bits for this tile (warps 0 and 1 fully participate)
    if (tid < 64) {
        int t = t0 + tid;
        bool g = (pad[b * Tv + t] == 0) && (upd[b * Tv + t] != 0);
        unsigned bal = __ballot_sync(0xffffffffu, g);
        if ((tid & 31) == 0) s_mask[tid >> 5] = bal;
    }
    __syncthreads();
    if (tid < 64) {
        unsigned m0 = s_mask[0], m1 = s_mask[1];
        int lt = tid & 31;
        bool g; int cnt;
        if (tid < 32) {
            g = (m0 >> lt) & 1u;
            unsigned hi = (lt == 31) ? 0u : (m0 >> (lt + 1));
            cnt = __popc(hi) + __popc(m1);
        } else {
            g = (m1 >> lt) & 1u;
            unsigned hi = (lt == 31) ? 0u : (m1 >> (lt + 1));
            cnt = __popc(hi);
        }
        s_coef[tid] = g ? (EPS * exp2f((float)cnt * LOG2_C)) : 0.0f;
        if (tid == 0) d_tilecnt[b * TILES + blockIdx.x] = __popc(m0) + __popc(m1);
    }
    __syncthreads();

    float4 wv[8];
#pragma unroll
    for (int j = 0; j < 8; j++) wv[j] = __ldg(&((const float4*)w)[j * 32 + lane]);

    float4 macc[8];
#pragma unroll
    for (int j = 0; j < 8; j++) macc[j] = make_float4(0.f, 0.f, 0.f, 0.f);

    for (int r = warp; r < TT; r += 8) {
        const int t = t0 + r;
        const float4* row = (const float4*)(x + ((size_t)(b * Tv + t)) * Dv);
        const float c = s_coef[r];
        float dot = 0.f;
#pragma unroll
        for (int j = 0; j < 8; j++) {
            float4 v = __ldcs(&row[j * 32 + lane]);   // read-once: stream past L2
            dot += v.x * wv[j].x + v.y * wv[j].y + v.z * wv[j].z + v.w * wv[j].w;
            macc[j].x += c * v.x;
            macc[j].y += c * v.y;
            macc[j].z += c * v.z;
            macc[j].w += c * v.w;
        }
#pragma unroll
        for (int off = 16; off; off >>= 1)
            dot += __shfl_down_sync(0xffffffffu, dot, off);
        if (lane == 0) d_y[b * Tv + t] = dot;
    }

    // combine 8 warps' memory partials deterministically via shared memory
    for (int wsel = 0; wsel < 8; wsel++) {
        if (warp == wsel) {
#pragma unroll
            for (int j = 0; j < 8; j++) {
                int d = j * 128 + lane * 4;
                if (wsel == 0) {
                    smem[d + 0] = macc[j].x; smem[d + 1] = macc[j].y;
                    smem[d + 2] = macc[j].z; smem[d + 3] = macc[j].w;
                } else {
                    smem[d + 0] += macc[j].x; smem[d + 1] += macc[j].y;
                    smem[d + 2] += macc[j].z; smem[d + 3] += macc[j].w;
                }
            }
        }
        __syncthreads();
    }
    float4* dst = (float4*)&d_mempart[((size_t)b * TILES + blockIdx.x) * Dv];
    const float4* s4 = (const float4*)smem;
    dst[tid] = s4[tid];  // 256 threads x float4 = 1024 floats
}

// ---------------------------------------------------------------------------
// Epilogue (fused): blocks 0..7  -> per-batch affine scan (float, shuffles)
//                   blocks 8..71 -> memory reduction with per-tile decay scale
// ---------------------------------------------------------------------------
__global__ void __launch_bounds__(256) epilogue_kernel(const int* __restrict__ pad,
                                                       const int* __restrict__ upd,
                                                       float* __restrict__ out) {
    const int tid = threadIdx.x;
    if (blockIdx.x < Bv) {
        // ---------------- scan: u_t = c_t*u_{t-1} + eps*g_t*y_t ----------
        const int b = blockIdx.x;
        const int warp = tid >> 5;
        const int lane = tid & 31;
        __shared__ float sWA[8];      // warp aggregate A
        __shared__ float sWC[8];      // warp aggregate C
        __shared__ float sWAe[8];     // warp exclusive prefix A

        // load 16 timesteps per thread
        bool gv[16]; bool pvb[16]; float yv[16];
        const int4* p4 = (const int4*)(pad + b * Tv);
        const int4* u4 = (const int4*)(upd + b * Tv);
#pragma unroll
        for (int q = 0; q < 4; q++) {
            int4 a = __ldg(&p4[tid * 4 + q]);
            int4 c = __ldg(&u4[tid * 4 + q]);
            int pa[4] = {a.x, a.y, a.z, a.w};
            int ua[4] = {c.x, c.y, c.z, c.w};
            float4 yq = *((const float4*)&d_y[b * Tv + tid * 16 + q * 4]);
            float ya[4] = {yq.x, yq.y, yq.z, yq.w};
#pragma unroll
            for (int r = 0; r < 4; r++) {
                pvb[q * 4 + r] = (pa[r] != 0);
                gv[q * 4 + r] = (pa[r] == 0) && (ua[r] != 0);
                yv[q * 4 + r] = ya[r];
            }
        }

        // compose affine transform over my 16 elems: u_out = C*u_in + A
        float C = 1.f, A = 0.f;
#pragma unroll
        for (int k = 0; k < 16; k++) {
            if (gv[k]) { A = 0.99f * A + 0.01f * yv[k]; C *= 0.99f; }
        }

        // warp inclusive scan of affine composition
#pragma unroll
        for (int off = 1; off < 32; off <<= 1) {
            float pC = __shfl_up_sync(0xffffffffu, C, off);
            float pA = __shfl_up_sync(0xffffffffu, A, off);
            float nA = fmaf(C, pA, A);
            float nC = C * pC;
            if (lane >= off) { A = nA; C = nC; }
        }
        // thread-exclusive within warp
        float eC = __shfl_up_sync(0xffffffffu, C, 1);
        float eA = __shfl_up_sync(0xffffffffu, A, 1);
        if (lane == 0) { eC = 1.f; eA = 0.f; }
        if (lane == 31) { sWC[warp] = C; sWA[warp] = A; }
        __syncthreads();
        if (tid == 0) {
            float c = 1.f, a = 0.f;
#pragma unroll
            for (int ww = 0; ww < 8; ww++) {
                sWAe[ww] = a;
                float nc = sWC[ww] * c;
                float na = fmaf(sWC[ww], a, sWA[ww]);
                c = nc; a = na;
            }
        }
        __syncthreads();

        // u at start of my 16 elems (u0 = 0)
        float u = fmaf(eC, sWAe[warp], eA);

        float ob[16];
#pragma unroll
        for (int k = 0; k < 16; k++) {
            if (gv[k]) u = fmaf(0.99f, u, 0.01f * yv[k]);
            float bias;
            if (pvb[k]) {
                bias = 1.0f;
            } else {
                bias = 1.0f + tanhf(u);
                bias = fminf(fmaxf(bias, 0.8f), 1.2f);
            }
            ob[k] = bias;
        }
        float4* o4 = (float4*)(out + b * Tv + tid * 16);
#pragma unroll
        for (int q = 0; q < 4; q++)
            o4[q] = make_float4(ob[q * 4], ob[q * 4 + 1], ob[q * 4 + 2], ob[q * 4 + 3]);
    } else {
        // ---------------- memred: memory[b,d] = sum_tiles scale_tile*partial ---
        const int m = blockIdx.x - Bv;          // 0..63
        const int oi = tid >> 3;                // 0..31
        const int sub = tid & 7;                // 0..7
        const int o4 = m * 32 + oi;             // float4 index over B*D
        const int b = o4 >> 8;                  // 256 float4 per batch (constant per block)
        const int d4 = o4 & 255;

        __shared__ int s_cnt[TILES];
        __shared__ float s_scale[TILES];
        if (tid < TILES) s_cnt[tid] = d_tilecnt[b * TILES + tid];
        __syncthreads();
        if (tid < TILES) {
            int after = 0;
            for (int j = tid + 1; j < TILES; j++) after += s_cnt[j];
            s_scale[tid] = (float)exp((double)after * LN_C);
        }
        __syncthreads();

        const float4* mp4 = (const float4*)d_mempart;
        float4 s = make_float4(0.f, 0.f, 0.f, 0.f);
#pragma unroll
        for (int k = 0; k < 8; k++) {
            int tile = sub * 8 + k;
            float sc = s_scale[tile];
            float4 v = mp4[((size_t)(b * TILES + tile)) * 256 + d4];
            s.x = fmaf(sc, v.x, s.x); s.y = fmaf(sc, v.y, s.y);
            s.z = fmaf(sc, v.z, s.z); s.w = fmaf(sc, v.w, s.w);
        }
        // reduce across sub (groups of 8 lanes) -- fixed tree, deterministic
#pragma unroll
        for (int off = 4; off; off >>= 1) {
            s.x += __shfl_down_sync(0xffffffffu, s.x, off);
            s.y += __shfl_down_sync(0xffffffffu, s.y, off);
            s.z += __shfl_down_sync(0xffffffffu, s.z, off);
            s.w += __shfl_down_sync(0xffffffffu, s.w, off);
        }
        if (sub == 0)
            ((float4*)(out + Bv * Tv))[o4] = s;
    }
}

// ---------------------------------------------------------------------------
extern "C" void kernel_launch(void* const* d_in, const int* in_sizes, int n_in,
                              void* d_out, int out_size) {
    const float* x = (const float*)d_in[0];            // write_signal (8,4096,1024)
    const int* pad = (const int*)d_in[1];              // pad_mask bool -> int32 (8,4096)
    const int* upd = (const int*)d_in[2];              // update_mask bool -> int32 (8,4096)
    const float* w = (const float*)d_in[3];            // w (1024,)
    float* out = (float*)d_out;                        // [bias (8*4096) | memory (8*1024)]

    dim3 grid(TILES, Bv);
    main_kernel<<<grid, 256>>>(x, w, pad, upd);
    epilogue_kernel<<<Bv + 64, 256>>>(pad, upd, out);
}